// round 2
// baseline (speedup 1.0000x reference)
#include <cuda_runtime.h>
#include <cuda_bf16.h>

// Problem constants (from reference)
#define NN   3072
#define DIMF 3
#define MK   3
#define EE   98304
#define CUM  36
#define HID  64
#define OUTD 5
#define ROWF 27648           // N*9 floats per R row
#define ROW4 6912            // float4s per R row
#define BT   288             // R-kernel block threads (288*4 = 1152, divisible by 9)
#define ITERS 24             // ROW4 / BT

// ---------------- scratch (__device__ globals; no allocation allowed) ----------------
__device__ __align__(16) float g_Ab[NN * 9];     // x_i @ W_sheaf[:3] + b_sheaf
__device__ __align__(16) float g_Bf[NN * 9];     // x_j @ W_sheaf[3:]
__device__ int   g_deg[NN];
__device__ int   g_cur[NN];
__device__ int   g_off[NN + 1];
__device__ int   g_csr[EE];
__device__ __align__(16) float g_out36[NN * 36]; // [h1 (9) | h2 (27)]

// ---------------- fast tanh: 2 MUFU + 3 FMA, ~1e-6 accurate ----------------
__device__ __forceinline__ float tanh_fast(float x) {
    float t = x * 2.885390081777927f;      // 2*log2(e)
    float e;
    asm("ex2.approx.ftz.f32 %0, %1;" : "=f"(e) : "f"(t));
    float r;
    asm("rcp.approx.ftz.f32 %0, %1;" : "=f"(r) : "f"(e + 1.0f));
    return fmaf(-2.0f, r, 1.0f);           // 1 - 2/(e^{2x}+1)
}

// ---------------- K0: per-node sheaf factors + zero counters ----------------
__global__ void k_prep(const float* __restrict__ x,
                       const float* __restrict__ Ws,   // [6,9]
                       const float* __restrict__ bs) { // [9]
    int n = blockIdx.x * blockDim.x + threadIdx.x;
    if (n >= NN) return;
    g_deg[n] = 0; g_cur[n] = 0;
    float x0 = x[n*3+0], x1 = x[n*3+1], x2 = x[n*3+2];
#pragma unroll
    for (int c = 0; c < 9; c++) {
        g_Ab[n*9+c] = fmaf(x0, Ws[c], fmaf(x1, Ws[9+c], fmaf(x2, Ws[18+c], bs[c])));
        g_Bf[n*9+c] = fmaf(x0, Ws[27+c], fmaf(x1, Ws[36+c], x2 * Ws[45+c]));
    }
}

// ---------------- K1: in-degree count (edge_index is int32, [2,E]) ----------------
__global__ void k_deg(const int* __restrict__ ei) {
    int e = blockIdx.x * blockDim.x + threadIdx.x;
    if (e < EE) atomicAdd(&g_deg[ei[EE + e]], 1);
}

// ---------------- K2: exclusive scan over 3072 degrees (single block) ----------------
__global__ void k_scan() {
    __shared__ int s[1024];
    int t = threadIdx.x;                       // 1024 threads, 3 elems each
    int a0 = g_deg[3*t], a1 = g_deg[3*t+1], a2 = g_deg[3*t+2];
    int loc = a0 + a1 + a2;
    s[t] = loc;
    __syncthreads();
    for (int off = 1; off < 1024; off <<= 1) {
        int v = (t >= off) ? s[t - off] : 0;
        __syncthreads();
        s[t] += v;
        __syncthreads();
    }
    int excl = s[t] - loc;
    g_off[3*t]   = excl;
    g_off[3*t+1] = excl + a0;
    g_off[3*t+2] = excl + a0 + a1;
    if (t == 1023) g_off[NN] = s[1023];
}

// ---------------- K3: CSR fill (by target) ----------------
__global__ void k_fill(const int* __restrict__ ei) {
    int e = blockIdx.x * blockDim.x + threadIdx.x;
    if (e >= EE) return;
    int t = ei[EE + e];
    int p = g_off[t] + atomicAdd(&g_cur[t], 1);
    g_csr[p] = e;
}

// ---------------- K4: hop 1: x(3ch) -> h1(9ch) ----------------
__global__ void k_hop1(const int* __restrict__ ei,
                       const float* __restrict__ x,
                       const float* __restrict__ Kv) {
    int n = blockIdx.x * blockDim.x + threadIdx.x;
    if (n >= NN) return;
    float acc[9];
#pragma unroll
    for (int c = 0; c < 9; c++) acc[c] = 0.f;
    int beg = g_off[n], end = g_off[n + 1];
    for (int p = beg; p < end; p++) {
        int e = g_csr[p];
        int s = ei[e];
        float xs0 = x[s*3+0], xs1 = x[s*3+1], xs2 = x[s*3+2];
        float k0 = Kv[e], k1 = Kv[EE + e], k2 = Kv[2*EE + e];
        acc[0] = fmaf(k0, xs0, acc[0]); acc[1] = fmaf(k0, xs1, acc[1]); acc[2] = fmaf(k0, xs2, acc[2]);
        acc[3] = fmaf(k1, xs0, acc[3]); acc[4] = fmaf(k1, xs1, acc[4]); acc[5] = fmaf(k1, xs2, acc[5]);
        acc[6] = fmaf(k2, xs0, acc[6]); acc[7] = fmaf(k2, xs1, acc[7]); acc[8] = fmaf(k2, xs2, acc[8]);
    }
#pragma unroll
    for (int c = 0; c < 9; c++) g_out36[n*36 + c] = acc[c];
}

// ---------------- K5: hop 2: h1(9ch) -> h2(27ch) ----------------
__global__ void k_hop2(const int* __restrict__ ei,
                       const float* __restrict__ Kv) {
    int n = blockIdx.x * blockDim.x + threadIdx.x;
    if (n >= NN) return;
    float acc[27];
#pragma unroll
    for (int c = 0; c < 27; c++) acc[c] = 0.f;
    int beg = g_off[n], end = g_off[n + 1];
    for (int p = beg; p < end; p++) {
        int e = g_csr[p];
        int s = ei[e];
        const float* hr = g_out36 + (size_t)s * 36;
        float4 h0 = *(const float4*)(hr);
        float4 h1v = *(const float4*)(hr + 4);
        float h8 = hr[8];
        float hv[9] = {h0.x, h0.y, h0.z, h0.w, h1v.x, h1v.y, h1v.z, h1v.w, h8};
        float k0 = Kv[e], k1 = Kv[EE + e], k2 = Kv[2*EE + e];
#pragma unroll
        for (int c = 0; c < 9; c++) {
            acc[c]      = fmaf(k0, hv[c], acc[c]);
            acc[9 + c]  = fmaf(k1, hv[c], acc[9 + c]);
            acc[18 + c] = fmaf(k2, hv[c], acc[18 + c]);
        }
    }
#pragma unroll
    for (int c = 0; c < 27; c++) g_out36[n*36 + 9 + c] = acc[c];
}

// ---------------- K6: fused GCN mean-agg + W_conv + MLP head ----------------
__global__ void k_head(const int* __restrict__ ei,
                       const float* __restrict__ Wc, const float* __restrict__ bc,
                       const float* __restrict__ W1, const float* __restrict__ b1,
                       const float* __restrict__ W2, const float* __restrict__ b2,
                       float* __restrict__ out) {
    int n = blockIdx.x * blockDim.x + threadIdx.x;
    if (n >= NN) return;
    float4 a[9];
#pragma unroll
    for (int q = 0; q < 9; q++) a[q] = make_float4(0.f, 0.f, 0.f, 0.f);
    int beg = g_off[n], end = g_off[n + 1];
    for (int p = beg; p < end; p++) {
        int e = g_csr[p];
        int s = ei[e];
        const float4* r = (const float4*)(g_out36 + (size_t)s * 36);
#pragma unroll
        for (int q = 0; q < 9; q++) {
            float4 v = r[q];
            a[q].x += v.x; a[q].y += v.y; a[q].z += v.z; a[q].w += v.w;
        }
    }
    float invd = 1.0f / fmaxf((float)(end - beg), 1.0f);
    float agg[36];
#pragma unroll
    for (int q = 0; q < 9; q++) {
        agg[4*q+0] = a[q].x * invd; agg[4*q+1] = a[q].y * invd;
        agg[4*q+2] = a[q].z * invd; agg[4*q+3] = a[q].w * invd;
    }
    float conv[36];
#pragma unroll 1
    for (int j = 0; j < 36; j++) {
        float s = bc[j];
#pragma unroll
        for (int c = 0; c < 36; c++) s = fmaf(agg[c], Wc[c*36 + j], s);
        conv[j] = fmaxf(s, 0.f);
    }
    float hid[64];
#pragma unroll 1
    for (int h = 0; h < 64; h++) {
        float s = b1[h];
#pragma unroll
        for (int j = 0; j < 36; j++) s = fmaf(conv[j], W1[j*64 + h], s);
        hid[h] = fmaxf(s, 0.f);
    }
#pragma unroll 1
    for (int t = 0; t < 5; t++) {
        float s = b2[t];
#pragma unroll
        for (int h = 0; h < 64; h++) s = fmaf(hid[h], W2[h*5 + t], s);
        out[(size_t)n * 5 + t] = s;
    }
}

// ---------------- K7: R = tanh(A_i + B_j + b) — the 340 MB kernel ----------------
__global__ __launch_bounds__(BT) void k_R(float* __restrict__ R) {
    int i = blockIdx.x;
    __shared__ float sA[9];
    if (threadIdx.x < 9) sA[threadIdx.x] = g_Ab[i * 9 + threadIdx.x];
    __syncthreads();
    int tid = threadIdx.x;
    int c0 = (4 * tid) % 9;                 // stride 288*4=1152 is divisible by 9
    float av0 = sA[c0];
    float av1 = sA[(c0 + 1) % 9];
    float av2 = sA[(c0 + 2) % 9];
    float av3 = sA[(c0 + 3) % 9];
    const float4* __restrict__ B = (const float4*)g_Bf;   // 110 KB, L1-resident
    float4* __restrict__ dst = (float4*)(R + (size_t)i * ROWF);
#pragma unroll 8
    for (int it = 0; it < ITERS; it++) {
        int idx = tid + it * BT;
        float4 b = B[idx];
        float4 o;
        o.x = tanh_fast(av0 + b.x);
        o.y = tanh_fast(av1 + b.y);
        o.z = tanh_fast(av2 + b.z);
        o.w = tanh_fast(av3 + b.w);
        __stcs(&dst[idx], o);               // streaming store: don't pollute L2
    }
}

// ---------------- launch ----------------
extern "C" void kernel_launch(void* const* d_in, const int* in_sizes, int n_in,
                              void* d_out, int out_size) {
    const float* x  = (const float*)d_in[0];
    const int*   ei = (const int*)d_in[1];      // int32 [2, E] (JAX x64 disabled)
    const float* Kv = (const float*)d_in[2];
    const float* Ws = (const float*)d_in[3];
    const float* bs = (const float*)d_in[4];
    const float* Wc = (const float*)d_in[5];
    const float* bc = (const float*)d_in[6];
    const float* W1 = (const float*)d_in[7];
    const float* b1 = (const float*)d_in[8];
    const float* W2 = (const float*)d_in[9];
    const float* b2 = (const float*)d_in[10];
    float* out = (float*)d_out;
    float* Rout = out + (size_t)NN * OUTD;   // out[3072,5] first, then R[3072,3072,3,3]

    k_prep<<<(NN + 255) / 256, 256>>>(x, Ws, bs);
    k_R<<<NN, BT>>>(Rout);                   // big one; independent of graph tail
    k_deg<<<(EE + 255) / 256, 256>>>(ei);
    k_scan<<<1, 1024>>>();
    k_fill<<<(EE + 255) / 256, 256>>>(ei);
    k_hop1<<<(NN + 255) / 256, 256>>>(ei, x, Kv);
    k_hop2<<<(NN + 255) / 256, 256>>>(ei, Kv);
    k_head<<<(NN + 255) / 256, 256>>>(ei, Wc, bc, W1, b1, W2, b2, out);
}

// round 3
// speedup vs baseline: 2.0944x; 2.0944x over previous
#include <cuda_runtime.h>
#include <cuda_bf16.h>

// Problem constants (from reference)
#define NN   3072
#define DIMF 3
#define MK   3
#define EE   98304
#define CUM  36
#define HID  64
#define OUTD 5
#define ROWF 27648           // N*9 floats per R row
#define ROW4 6912            // float4s per R row
#define BT   288             // R-kernel block threads (288*4 = 1152, divisible by 9)
#define ITERS 24             // ROW4 / BT

// ---------------- scratch (__device__ globals; no allocation allowed) ----------------
__device__ __align__(16) float g_Ab[NN * 9];     // x_i @ W_sheaf[:3] + b_sheaf
__device__ __align__(16) float g_Bf[NN * 9];     // x_j @ W_sheaf[3:]
__device__ int   g_deg[NN];
__device__ int   g_cur[NN];
__device__ int   g_off[NN + 1];
__device__ int   g_csr[EE];
__device__ __align__(16) float g_out36[NN * 36]; // [h1 (9) | h2 (27)]

// ---------------- fast tanh: 2 MUFU + 3 FMA, ~1e-6 accurate ----------------
__device__ __forceinline__ float tanh_fast(float x) {
    float t = x * 2.885390081777927f;      // 2*log2(e)
    float e;
    asm("ex2.approx.ftz.f32 %0, %1;" : "=f"(e) : "f"(t));
    float r;
    asm("rcp.approx.ftz.f32 %0, %1;" : "=f"(r) : "f"(e + 1.0f));
    return fmaf(-2.0f, r, 1.0f);           // 1 - 2/(e^{2x}+1)
}

// ---------------- K0: per-node sheaf factors + zero counters ----------------
__global__ void k_prep(const float* __restrict__ x,
                       const float* __restrict__ Ws,   // [6,9]
                       const float* __restrict__ bs) { // [9]
    int n = blockIdx.x * blockDim.x + threadIdx.x;
    if (n >= NN) return;
    g_deg[n] = 0; g_cur[n] = 0;
    float x0 = x[n*3+0], x1 = x[n*3+1], x2 = x[n*3+2];
#pragma unroll
    for (int c = 0; c < 9; c++) {
        g_Ab[n*9+c] = fmaf(x0, Ws[c], fmaf(x1, Ws[9+c], fmaf(x2, Ws[18+c], bs[c])));
        g_Bf[n*9+c] = fmaf(x0, Ws[27+c], fmaf(x1, Ws[36+c], x2 * Ws[45+c]));
    }
}

// ---------------- K1: in-degree count (edge_index int32 [2,E]) ----------------
__global__ void k_deg(const int* __restrict__ ei) {
    int e = blockIdx.x * blockDim.x + threadIdx.x;
    if (e < EE) atomicAdd(&g_deg[ei[EE + e]], 1);
}

// ---------------- K2: exclusive scan over 3072 degrees (single block) ----------------
__global__ void k_scan() {
    __shared__ int s[1024];
    int t = threadIdx.x;                       // 1024 threads, 3 elems each
    int a0 = g_deg[3*t], a1 = g_deg[3*t+1], a2 = g_deg[3*t+2];
    int loc = a0 + a1 + a2;
    s[t] = loc;
    __syncthreads();
    for (int off = 1; off < 1024; off <<= 1) {
        int v = (t >= off) ? s[t - off] : 0;
        __syncthreads();
        s[t] += v;
        __syncthreads();
    }
    int excl = s[t] - loc;
    g_off[3*t]   = excl;
    g_off[3*t+1] = excl + a0;
    g_off[3*t+2] = excl + a0 + a1;
    if (t == 1023) g_off[NN] = s[1023];
}

// ---------------- K3: CSR fill (by target) ----------------
__global__ void k_fill(const int* __restrict__ ei) {
    int e = blockIdx.x * blockDim.x + threadIdx.x;
    if (e >= EE) return;
    int t = ei[EE + e];
    int p = g_off[t] + atomicAdd(&g_cur[t], 1);
    g_csr[p] = e;
}

// ---------------- K4: hop 1 (warp per node): x(3ch) -> h1(9ch) ----------------
__global__ void k_hop1(const int* __restrict__ ei,
                       const float* __restrict__ x,
                       const float* __restrict__ Kv) {
    int warp = (blockIdx.x * blockDim.x + threadIdx.x) >> 5;
    int lane = threadIdx.x & 31;
    if (warp >= NN) return;
    int n = warp;
    float acc[9];
#pragma unroll
    for (int c = 0; c < 9; c++) acc[c] = 0.f;
    int beg = g_off[n], end = g_off[n + 1];
    for (int p = beg + lane; p < end; p += 32) {
        int e = g_csr[p];
        int s = ei[e];
        float xs0 = __ldg(&x[s*3+0]), xs1 = __ldg(&x[s*3+1]), xs2 = __ldg(&x[s*3+2]);
        float k0 = Kv[e], k1 = Kv[EE + e], k2 = Kv[2*EE + e];
        acc[0] = fmaf(k0, xs0, acc[0]); acc[1] = fmaf(k0, xs1, acc[1]); acc[2] = fmaf(k0, xs2, acc[2]);
        acc[3] = fmaf(k1, xs0, acc[3]); acc[4] = fmaf(k1, xs1, acc[4]); acc[5] = fmaf(k1, xs2, acc[5]);
        acc[6] = fmaf(k2, xs0, acc[6]); acc[7] = fmaf(k2, xs1, acc[7]); acc[8] = fmaf(k2, xs2, acc[8]);
    }
#pragma unroll
    for (int off = 16; off; off >>= 1)
#pragma unroll
        for (int c = 0; c < 9; c++) acc[c] += __shfl_xor_sync(0xffffffffu, acc[c], off);
    if (lane == 0) {
        float* dst = g_out36 + (size_t)n * 36;
        *(float4*)(dst)     = make_float4(acc[0], acc[1], acc[2], acc[3]);
        *(float4*)(dst + 4) = make_float4(acc[4], acc[5], acc[6], acc[7]);
        dst[8] = acc[8];
    }
}

// ---------------- K5: hop 2 (warp per node): h1(9ch) -> h2(27ch) ----------------
__global__ void k_hop2(const int* __restrict__ ei,
                       const float* __restrict__ Kv) {
    int warp = (blockIdx.x * blockDim.x + threadIdx.x) >> 5;
    int lane = threadIdx.x & 31;
    if (warp >= NN) return;
    int n = warp;
    float acc[27];
#pragma unroll
    for (int c = 0; c < 27; c++) acc[c] = 0.f;
    int beg = g_off[n], end = g_off[n + 1];
    for (int p = beg + lane; p < end; p += 32) {
        int e = g_csr[p];
        int s = ei[e];
        const float* hr = g_out36 + (size_t)s * 36;
        float4 h0 = *(const float4*)(hr);
        float4 h1v = *(const float4*)(hr + 4);
        float h8 = hr[8];
        float hv[9] = {h0.x, h0.y, h0.z, h0.w, h1v.x, h1v.y, h1v.z, h1v.w, h8};
        float k0 = Kv[e], k1 = Kv[EE + e], k2 = Kv[2*EE + e];
#pragma unroll
        for (int c = 0; c < 9; c++) {
            acc[c]      = fmaf(k0, hv[c], acc[c]);
            acc[9 + c]  = fmaf(k1, hv[c], acc[9 + c]);
            acc[18 + c] = fmaf(k2, hv[c], acc[18 + c]);
        }
    }
#pragma unroll
    for (int off = 16; off; off >>= 1)
#pragma unroll
        for (int c = 0; c < 27; c++) acc[c] += __shfl_xor_sync(0xffffffffu, acc[c], off);
    if (lane == 0) {
        float* dst = g_out36 + (size_t)n * 36 + 9;
#pragma unroll
        for (int c = 0; c < 27; c++) dst[c] = acc[c];
    }
}

// ---------------- K6: fused GCN mean-agg + W_conv + MLP head (warp per node) ----------
__global__ __launch_bounds__(256) void k_head(
                       const int* __restrict__ ei,
                       const float* __restrict__ Wc, const float* __restrict__ bc,
                       const float* __restrict__ W1, const float* __restrict__ b1,
                       const float* __restrict__ W2, const float* __restrict__ b2,
                       float* __restrict__ out) {
    __shared__ float sconv[8][36];
    __shared__ float shid[8][64];
    int w = threadIdx.x >> 5;                  // warp in block
    int lane = threadIdx.x & 31;
    int n = blockIdx.x * 8 + w;
    if (n >= NN) return;
    float acc[36];
#pragma unroll
    for (int c = 0; c < 36; c++) acc[c] = 0.f;
    int beg = g_off[n], end = g_off[n + 1];
    for (int p = beg + lane; p < end; p += 32) {
        int e = g_csr[p];
        int s = ei[e];
        const float4* r = (const float4*)(g_out36 + (size_t)s * 36);
#pragma unroll
        for (int q = 0; q < 9; q++) {
            float4 v = r[q];
            acc[4*q+0] += v.x; acc[4*q+1] += v.y; acc[4*q+2] += v.z; acc[4*q+3] += v.w;
        }
    }
#pragma unroll
    for (int off = 16; off; off >>= 1)
#pragma unroll
        for (int c = 0; c < 36; c++) acc[c] += __shfl_xor_sync(0xffffffffu, acc[c], off);
    // every lane now holds the full 36-channel sum
    float invd = 1.0f / fmaxf((float)(end - beg), 1.0f);
#pragma unroll
    for (int c = 0; c < 36; c++) acc[c] *= invd;
    // conv: lane handles output channels {lane, lane+32}
#pragma unroll
    for (int jb = 0; jb < 2; jb++) {
        int j = lane + 32 * jb;
        if (j < 36) {
            float s = bc[j];
#pragma unroll
            for (int c = 0; c < 36; c++) s = fmaf(acc[c], Wc[c*36 + j], s);
            sconv[w][j] = fmaxf(s, 0.f);
        }
    }
    __syncwarp();
    // hid: lane handles {lane, lane+32}
#pragma unroll
    for (int hb = 0; hb < 2; hb++) {
        int h = lane + 32 * hb;
        float s = b1[h];
#pragma unroll
        for (int j = 0; j < 36; j++) s = fmaf(sconv[w][j], W1[j*64 + h], s);
        shid[w][h] = fmaxf(s, 0.f);
    }
    __syncwarp();
    if (lane < OUTD) {
        float s = b2[lane];
#pragma unroll
        for (int h = 0; h < 64; h++) s = fmaf(shid[w][h], W2[h*5 + lane], s);
        out[(size_t)n * 5 + lane] = s;
    }
}

// ---------------- K7: R = tanh(A_i + B_j + b) — the 340 MB kernel ----------------
__global__ __launch_bounds__(BT) void k_R(float* __restrict__ R) {
    int i = blockIdx.x;
    __shared__ float sA[9];
    if (threadIdx.x < 9) sA[threadIdx.x] = g_Ab[i * 9 + threadIdx.x];
    __syncthreads();
    int tid = threadIdx.x;
    int c0 = (4 * tid) % 9;                 // stride 288*4=1152 is divisible by 9
    float av0 = sA[c0];
    float av1 = sA[(c0 + 1) % 9];
    float av2 = sA[(c0 + 2) % 9];
    float av3 = sA[(c0 + 3) % 9];
    const float4* __restrict__ B = (const float4*)g_Bf;   // 110 KB, L1-resident
    float4* __restrict__ dst = (float4*)(R + (size_t)i * ROWF);
#pragma unroll 8
    for (int it = 0; it < ITERS; it++) {
        int idx = tid + it * BT;
        float4 b = B[idx];
        float4 o;
        o.x = tanh_fast(av0 + b.x);
        o.y = tanh_fast(av1 + b.y);
        o.z = tanh_fast(av2 + b.z);
        o.w = tanh_fast(av3 + b.w);
        __stcs(&dst[idx], o);               // streaming store: don't pollute L2
    }
}

// ---------------- launch ----------------
extern "C" void kernel_launch(void* const* d_in, const int* in_sizes, int n_in,
                              void* d_out, int out_size) {
    const float* x  = (const float*)d_in[0];
    const int*   ei = (const int*)d_in[1];      // int32 [2, E]
    const float* Kv = (const float*)d_in[2];
    const float* Ws = (const float*)d_in[3];
    const float* bs = (const float*)d_in[4];
    const float* Wc = (const float*)d_in[5];
    const float* bc = (const float*)d_in[6];
    const float* W1 = (const float*)d_in[7];
    const float* b1 = (const float*)d_in[8];
    const float* W2 = (const float*)d_in[9];
    const float* b2 = (const float*)d_in[10];
    float* out = (float*)d_out;
    float* Rout = out + (size_t)NN * OUTD;   // out[3072,5] first, then R[3072,3072,3,3]

    k_prep<<<(NN + 255) / 256, 256>>>(x, Ws, bs);
    k_R<<<NN, BT>>>(Rout);                   // the big store-bound kernel
    k_deg<<<(EE + 255) / 256, 256>>>(ei);
    k_scan<<<1, 1024>>>();
    k_fill<<<(EE + 255) / 256, 256>>>(ei);
    k_hop1<<<NN / 8, 256>>>(ei, x, Kv);      // warp per node
    k_hop2<<<NN / 8, 256>>>(ei, Kv);         // warp per node
    k_head<<<NN / 8, 256>>>(ei, Wc, bc, W1, b1, W2, b2, out);
}

// round 6
// speedup vs baseline: 2.4030x; 1.1474x over previous
#include <cuda_runtime.h>
#include <cuda_bf16.h>

// Problem constants
#define NN    3072
#define EE    98304
#define OUTD  5
#define ROWF  27648          // N*9 floats per R row
#define BT    288            // threads per block (288*4 = 1152, divisible by 9)
#define ITERS 24             // 6912 float4s / 288
#define TAILB 96             // tail worker blocks (must all fit in wave 1)
#define TAILT (TAILB*BT)     // 27648 tail threads
#define TAILW (TAILB*9)      // 864 tail warps

// ---------------- scratch ----------------
__device__ __align__(16) float g_Ab[NN * 9];
__device__ __align__(16) float g_Bf[NN * 9];
__device__ int   g_deg[NN];
__device__ int   g_cur[NN];
__device__ int   g_off[NN + 1];
__device__ int   g_csr[EE];
__device__ __align__(16) float g_out36[NN * 36];
__device__ int   g_bar_cnt;
__device__ int   g_bar_phase;

// ---------------- fast tanh: 2 MUFU + 3 FMA ----------------
__device__ __forceinline__ float tanh_fast(float x) {
    float t = x * 2.885390081777927f;
    float e;
    asm("ex2.approx.ftz.f32 %0, %1;" : "=f"(e) : "f"(t));
    float r;
    asm("rcp.approx.ftz.f32 %0, %1;" : "=f"(r) : "f"(e + 1.0f));
    return fmaf(-2.0f, r, 1.0f);
}

// ---------------- global spin barrier among TAILB blocks ----------------
__device__ __forceinline__ void tail_barrier() {
    __syncthreads();
    if (threadIdx.x == 0) {
        __threadfence();
        int ph = atomicAdd(&g_bar_phase, 0);
        int old = atomicAdd(&g_bar_cnt, 1);
        if (old == TAILB - 1) {
            g_bar_cnt = 0;
            __threadfence();
            atomicAdd(&g_bar_phase, 1);
        } else {
            while (atomicAdd(&g_bar_phase, 0) == ph) { }
        }
        __threadfence();
    }
    __syncthreads();
}

// ---------------- K0: per-node sheaf factors + zero counters ----------------
__global__ void k_prep(const float* __restrict__ x,
                       const float* __restrict__ Ws,
                       const float* __restrict__ bs) {
    int n = blockIdx.x * blockDim.x + threadIdx.x;
    if (n >= NN) return;
    if (n == 0) g_bar_cnt = 0;
    g_deg[n] = 0; g_cur[n] = 0;
    float x0 = x[n*3+0], x1 = x[n*3+1], x2 = x[n*3+2];
#pragma unroll
    for (int c = 0; c < 9; c++) {
        g_Ab[n*9+c] = fmaf(x0, Ws[c], fmaf(x1, Ws[9+c], fmaf(x2, Ws[18+c], bs[c])));
        g_Bf[n*9+c] = fmaf(x0, Ws[27+c], fmaf(x1, Ws[36+c], x2 * Ws[45+c]));
    }
}

// ---------------- fused: tail pipeline (blocks 0..95) + R rows (blocks 96..3167) ----
__global__ __launch_bounds__(BT) void k_fused(
        const float* __restrict__ x,
        const int*   __restrict__ ei,
        const float* __restrict__ Kv,
        const float* __restrict__ Wc, const float* __restrict__ bc,
        const float* __restrict__ W1, const float* __restrict__ b1,
        const float* __restrict__ W2, const float* __restrict__ b2,
        float* __restrict__ out, float* __restrict__ R) {
    int tid = threadIdx.x;

    if (blockIdx.x >= TAILB) {
        // ---------------- R writer block ----------------
        int i = blockIdx.x - TAILB;
        __shared__ float sA[9];
        if (tid < 9) sA[tid] = g_Ab[i * 9 + tid];
        __syncthreads();
        int c0 = (4 * tid) % 9;
        float av0 = sA[c0];
        float av1 = sA[(c0 + 1) % 9];
        float av2 = sA[(c0 + 2) % 9];
        float av3 = sA[(c0 + 3) % 9];
        const float4* __restrict__ B = (const float4*)g_Bf;
        float4* __restrict__ dst = (float4*)(R + (size_t)i * ROWF);
#pragma unroll 8
        for (int it = 0; it < ITERS; it++) {
            int idx = tid + it * BT;
            float4 b = B[idx];
            float4 o;
            o.x = tanh_fast(av0 + b.x);
            o.y = tanh_fast(av1 + b.y);
            o.z = tanh_fast(av2 + b.z);
            o.w = tanh_fast(av3 + b.w);
            __stcs(&dst[idx], o);
        }
        return;
    }

    // ---------------- tail worker block ----------------
    int bid  = blockIdx.x;
    int gtid = bid * BT + tid;           // 0..27647
    int lane = tid & 31;
    int wid  = tid >> 5;                 // 0..8
    int gw   = bid * 9 + wid;            // 0..863

    __shared__ int   wsum[10];
    __shared__ float sconv[9][36];
    __shared__ float shid[9][64];

    // --- Stage A: in-degree count ---
    for (int e = gtid; e < EE; e += TAILT)
        atomicAdd(&g_deg[ei[EE + e]], 1);
    tail_barrier();

    // --- Stage B: exclusive scan (block 0 only) ---
    if (bid == 0) {
        const int D = 11;                // 288*11 = 3168 >= 3072
        int base = tid * D;
        int vals[D];
        int sum = 0;
#pragma unroll
        for (int k = 0; k < D; k++) {
            int idx = base + k;
            int v = (idx < NN) ? g_deg[idx] : 0;
            vals[k] = sum; sum += v;
        }
        // warp inclusive scan of per-thread sums
        int incl = sum;
#pragma unroll
        for (int off = 1; off < 32; off <<= 1) {
            int v = __shfl_up_sync(0xffffffffu, incl, off);
            if (lane >= off) incl += v;
        }
        if (lane == 31) wsum[wid] = incl;
        __syncthreads();
        if (tid == 0) {
            int run = 0;
#pragma unroll
            for (int i2 = 0; i2 < 9; i2++) { int v = wsum[i2]; wsum[i2] = run; run += v; }
            g_off[NN] = run;
        }
        __syncthreads();
        int tOff = wsum[wid] + (incl - sum);   // exclusive prefix for this thread
#pragma unroll
        for (int k = 0; k < D; k++) {
            int idx = base + k;
            if (idx < NN) g_off[idx] = tOff + vals[k];
        }
    }
    tail_barrier();

    // --- Stage C: CSR fill ---
    for (int e = gtid; e < EE; e += TAILT) {
        int t = ei[EE + e];
        int p = g_off[t] + atomicAdd(&g_cur[t], 1);
        g_csr[p] = e;
    }
    tail_barrier();

    // --- Stage D: hop 1 (warp per node, ~3.5 nodes per warp) ---
    for (int n = gw; n < NN; n += TAILW) {
        float acc[9];
#pragma unroll
        for (int c = 0; c < 9; c++) acc[c] = 0.f;
        int beg = g_off[n], end = g_off[n + 1];
        for (int p = beg + lane; p < end; p += 32) {
            int e = g_csr[p];
            int s = ei[e];
            float xs0 = __ldg(&x[s*3+0]), xs1 = __ldg(&x[s*3+1]), xs2 = __ldg(&x[s*3+2]);
            float k0 = Kv[e], k1 = Kv[EE + e], k2 = Kv[2*EE + e];
            acc[0] = fmaf(k0, xs0, acc[0]); acc[1] = fmaf(k0, xs1, acc[1]); acc[2] = fmaf(k0, xs2, acc[2]);
            acc[3] = fmaf(k1, xs0, acc[3]); acc[4] = fmaf(k1, xs1, acc[4]); acc[5] = fmaf(k1, xs2, acc[5]);
            acc[6] = fmaf(k2, xs0, acc[6]); acc[7] = fmaf(k2, xs1, acc[7]); acc[8] = fmaf(k2, xs2, acc[8]);
        }
#pragma unroll
        for (int off = 16; off; off >>= 1)
#pragma unroll
            for (int c = 0; c < 9; c++) acc[c] += __shfl_xor_sync(0xffffffffu, acc[c], off);
        if (lane == 0) {
            float* dst = g_out36 + (size_t)n * 36;
            *(float4*)(dst)     = make_float4(acc[0], acc[1], acc[2], acc[3]);
            *(float4*)(dst + 4) = make_float4(acc[4], acc[5], acc[6], acc[7]);
            dst[8] = acc[8];
        }
    }
    tail_barrier();

    // --- Stage E: hop 2 ---
    for (int n = gw; n < NN; n += TAILW) {
        float acc[27];
#pragma unroll
        for (int c = 0; c < 27; c++) acc[c] = 0.f;
        int beg = g_off[n], end = g_off[n + 1];
        for (int p = beg + lane; p < end; p += 32) {
            int e = g_csr[p];
            int s = ei[e];
            const float* hr = g_out36 + (size_t)s * 36;
            float4 h0 = *(const float4*)(hr);
            float4 h1v = *(const float4*)(hr + 4);
            float h8 = hr[8];
            float hv[9] = {h0.x, h0.y, h0.z, h0.w, h1v.x, h1v.y, h1v.z, h1v.w, h8};
            float k0 = Kv[e], k1 = Kv[EE + e], k2 = Kv[2*EE + e];
#pragma unroll
            for (int c = 0; c < 9; c++) {
                acc[c]      = fmaf(k0, hv[c], acc[c]);
                acc[9 + c]  = fmaf(k1, hv[c], acc[9 + c]);
                acc[18 + c] = fmaf(k2, hv[c], acc[18 + c]);
            }
        }
#pragma unroll
        for (int off = 16; off; off >>= 1)
#pragma unroll
            for (int c = 0; c < 27; c++) acc[c] += __shfl_xor_sync(0xffffffffu, acc[c], off);
        if (lane == 0) {
            float* dst = g_out36 + (size_t)n * 36 + 9;
#pragma unroll
            for (int c = 0; c < 27; c++) dst[c] = acc[c];
        }
    }
    tail_barrier();

    // --- Stage F: GCN mean-agg + W_conv + MLP head ---
    for (int n = gw; n < NN; n += TAILW) {
        float acc[36];
#pragma unroll
        for (int c = 0; c < 36; c++) acc[c] = 0.f;
        int beg = g_off[n], end = g_off[n + 1];
        for (int p = beg + lane; p < end; p += 32) {
            int e = g_csr[p];
            int s = ei[e];
            const float4* r = (const float4*)(g_out36 + (size_t)s * 36);
#pragma unroll
            for (int q = 0; q < 9; q++) {
                float4 v = r[q];
                acc[4*q+0] += v.x; acc[4*q+1] += v.y; acc[4*q+2] += v.z; acc[4*q+3] += v.w;
            }
        }
#pragma unroll
        for (int off = 16; off; off >>= 1)
#pragma unroll
            for (int c = 0; c < 36; c++) acc[c] += __shfl_xor_sync(0xffffffffu, acc[c], off);
        float invd = 1.0f / fmaxf((float)(end - beg), 1.0f);
#pragma unroll
        for (int c = 0; c < 36; c++) acc[c] *= invd;
#pragma unroll
        for (int jb = 0; jb < 2; jb++) {
            int j = lane + 32 * jb;
            if (j < 36) {
                float s = bc[j];
#pragma unroll
                for (int c = 0; c < 36; c++) s = fmaf(acc[c], Wc[c*36 + j], s);
                sconv[wid][j] = fmaxf(s, 0.f);
            }
        }
        __syncwarp();
#pragma unroll
        for (int hb = 0; hb < 2; hb++) {
            int h = lane + 32 * hb;
            float s = b1[h];
#pragma unroll
            for (int j = 0; j < 36; j++) s = fmaf(sconv[wid][j], W1[j*64 + h], s);
            shid[wid][h] = fmaxf(s, 0.f);
        }
        __syncwarp();
        if (lane < OUTD) {
            float s = b2[lane];
#pragma unroll
            for (int h = 0; h < 64; h++) s = fmaf(shid[wid][h], W2[h*5 + lane], s);
            out[(size_t)n * 5 + lane] = s;
        }
        __syncwarp();
    }
}

// ---------------- launch ----------------
extern "C" void kernel_launch(void* const* d_in, const int* in_sizes, int n_in,
                              void* d_out, int out_size) {
    const float* x  = (const float*)d_in[0];
    const int*   ei = (const int*)d_in[1];      // int32 [2, E]
    const float* Kv = (const float*)d_in[2];
    const float* Ws = (const float*)d_in[3];
    const float* bs = (const float*)d_in[4];
    const float* Wc = (const float*)d_in[5];
    const float* bc = (const float*)d_in[6];
    const float* W1 = (const float*)d_in[7];
    const float* b1 = (const float*)d_in[8];
    const float* W2 = (const float*)d_in[9];
    const float* b2 = (const float*)d_in[10];
    float* out  = (float*)d_out;
    float* Rout = out + (size_t)NN * OUTD;

    k_prep<<<(NN + 255) / 256, 256>>>(x, Ws, bs);
    k_fused<<<TAILB + NN, BT>>>(x, ei, Kv, Wc, bc, W1, b1, W2, b2, out, Rout);
}